// round 9
// baseline (speedup 1.0000x reference)
#include <cuda_runtime.h>
#include <cuda_bf16.h>
#include <cstdint>

#define BATCH 256
#define NN 256
#define MM 256
#define DIM 32
#define BIGF 1e8f

// dist row-major per batch: [b][r*256 + c]
__device__ float g_dist[BATCH * NN * MM];
__device__ float g_partial[BATCH];

__device__ __forceinline__ uint32_t smem_u32(const void* p) {
    uint32_t a;
    asm("{ .reg .u64 t; cvta.to.shared.u64 t, %1; cvt.u32.u64 %0, t; }" : "=r"(a) : "l"(p));
    return a;
}
__device__ __forceinline__ void ldmx4(uint32_t* r, uint32_t addr) {
    asm volatile("ldmatrix.sync.aligned.m8n8.x4.shared.b16 {%0,%1,%2,%3}, [%4];"
                 : "=r"(r[0]), "=r"(r[1]), "=r"(r[2]), "=r"(r[3]) : "r"(addr));
}
__device__ __forceinline__ void mma16816(float* c, const uint32_t* a, uint32_t b0,
                                         uint32_t b1) {
    asm volatile(
        "mma.sync.aligned.m16n8k16.row.col.f32.bf16.bf16.f32 "
        "{%0,%1,%2,%3}, {%4,%5,%6,%7}, {%8,%9}, {%0,%1,%2,%3};"
        : "+f"(c[0]), "+f"(c[1]), "+f"(c[2]), "+f"(c[3])
        : "r"(a[0]), "r"(a[1]), "r"(a[2]), "r"(a[3]), "r"(b0), "r"(b1));
}

#define PITCHB 80   // bytes per bf16 row (40 bf16); 8-row ldmatrix conflict-free

// ---------------------------------------------------------------------------
// Kernel 1: dist via mma.sync bf16 (row-major output; 19.6us, L2-resident).
// ---------------------------------------------------------------------------
__global__ __launch_bounds__(256) void dist_kernel(const float* __restrict__ x,
                                                   const float* __restrict__ y) {
    __shared__ __align__(16) char xs[256 * PITCHB];
    __shared__ __align__(16) char ys[256 * PITCHB];
    __shared__ float x2s[256];
    __shared__ float y2s[256];

    const int b = blockIdx.x, t = threadIdx.x;
    const int w = t >> 5, lane = t & 31;
    const float* xr = x + ((size_t)b * NN + t) * DIM;
    const float* yr = y + ((size_t)b * MM + t) * DIM;

    {
        float sx = 0.f, sy = 0.f;
#pragma unroll
        for (int q = 0; q < 8; q++) {
            float4 v = *(const float4*)(xr + q * 4);
            sx = fmaf(v.x, v.x, fmaf(v.y, v.y, fmaf(v.z, v.z, fmaf(v.w, v.w, sx))));
            uint2 wv;
            asm("cvt.rn.bf16x2.f32 %0, %1, %2;" : "=r"(wv.x) : "f"(v.y), "f"(v.x));
            asm("cvt.rn.bf16x2.f32 %0, %1, %2;" : "=r"(wv.y) : "f"(v.w), "f"(v.z));
            *(uint2*)(xs + t * PITCHB + q * 8) = wv;
            float4 u = *(const float4*)(yr + q * 4);
            sy = fmaf(u.x, u.x, fmaf(u.y, u.y, fmaf(u.z, u.z, fmaf(u.w, u.w, sy))));
            uint2 uv;
            asm("cvt.rn.bf16x2.f32 %0, %1, %2;" : "=r"(uv.x) : "f"(u.y), "f"(u.x));
            asm("cvt.rn.bf16x2.f32 %0, %1, %2;" : "=r"(uv.y) : "f"(u.w), "f"(u.z));
            *(uint2*)(ys + t * PITCHB + q * 8) = uv;
        }
        x2s[t] = sx;
        y2s[t] = sy;
    }
    __syncthreads();

    const uint32_t xsb = smem_u32(xs), ysb = smem_u32(ys);
    const int i0w = w * 32;

    uint32_t afr[2][2][4];
    {
        int rowA = i0w + (lane & 15);
        uint32_t base = xsb + rowA * PITCHB + ((lane >> 4) << 4);
#pragma unroll
        for (int rt = 0; rt < 2; rt++)
#pragma unroll
            for (int ks = 0; ks < 2; ks++)
                ldmx4(afr[rt][ks], base + rt * 16 * PITCHB + ks * 32);
    }

    float* gb = g_dist + (size_t)b * (NN * MM);
    const int rsub = lane >> 2;
    const int cpair = 2 * (lane & 3);

    for (int cg = 0; cg < 16; cg++) {
        const int c0 = cg * 16;
        uint32_t bbase = ysb + (c0 + (lane & 7) + ((lane & 16) >> 1)) * PITCHB +
                         ((lane >> 3) & 1) * 16;
        uint32_t b_k0[4], b_k1[4];
        ldmx4(b_k0, bbase);
        ldmx4(b_k1, bbase + 32);

#pragma unroll
        for (int rt = 0; rt < 2; rt++) {
            float C0[4] = {0.f, 0.f, 0.f, 0.f};
            float C1[4] = {0.f, 0.f, 0.f, 0.f};
            mma16816(C0, afr[rt][0], b_k0[0], b_k0[1]);
            mma16816(C0, afr[rt][1], b_k1[0], b_k1[1]);
            mma16816(C1, afr[rt][0], b_k0[2], b_k0[3]);
            mma16816(C1, afr[rt][1], b_k1[2], b_k1[3]);

            const int r_lo = i0w + rt * 16 + rsub;
            const float x2lo = x2s[r_lo], x2hi = x2s[r_lo + 8];
#pragma unroll
            for (int nt = 0; nt < 2; nt++) {
                const float* C = nt ? C1 : C0;
                const int cc = c0 + nt * 8 + cpair;
                float2 yy = *(const float2*)(y2s + cc);
                float2 olo, ohi;
                olo.x = fmaxf(fmaf(-2.f, C[0], x2lo + yy.x), 0.f);
                olo.y = fmaxf(fmaf(-2.f, C[1], x2lo + yy.y), 0.f);
                ohi.x = fmaxf(fmaf(-2.f, C[2], x2hi + yy.x), 0.f);
                ohi.y = fmaxf(fmaf(-2.f, C[3], x2hi + yy.y), 0.f);
                *(float2*)(gb + r_lo * 256 + cc) = olo;
                *(float2*)(gb + (r_lo + 8) * 256 + cc) = ohi;
            }
        }
    }
}

// ---------------------------------------------------------------------------
// Kernel 2: row-pipelined systolic DP. 128 CTAs x 256 threads, 2 batches/CTA.
// Lane l of warp w owns dist-row r=32w+l (D-row r+1), sweeping columns.
// left = register; up/diag from lane l-1 via shfl of 1/2-step-old values
// (latency hidden). Warp w lags warp w-1 by 48 steps; boundary row flows
// through a 128-slot smem ring; __syncthreads every 16 steps (39 phases).
// dist prefetched into lane-private 64-col smem windows via cp.async.
// FIX vs R8: pre-loop cp.async group loads the initial window [0,16)
// (warp 0 otherwise never receives columns 0-15 -> garbage dist).
// ---------------------------------------------------------------------------
#define NPH 39
#define DW_FLOATS (2 * 8 * 2048)      // [bat][warp][lane*64 + (c&63)]
#define RING_FLOATS2 (2 * 8 * 128)    // [bat][warp][c&127]
#define SMEM_DP ((DW_FLOATS + RING_FLOATS2) * 4)

__global__ __launch_bounds__(256) void dtw_kernel() {
    extern __shared__ float sm[];
    float* dw = sm;
    float* ring = sm + DW_FLOATS;
    const int bb = blockIdx.x, t = threadIdx.x;
    const int w = t >> 5, l = t & 31;

    const float* gb0 = g_dist + (size_t)(2 * bb) * 65536 + t * 256;
    const float* gb1 = gb0 + 65536;
    float* dwr0 = dw + w * 2048 + l * 64;
    float* dwr1 = dwr0 + 8 * 2048;
    const uint32_t dws0 = smem_u32(dwr0);
    const uint32_t dws1 = smem_u32(dwr1);
    float* ringw0 = ring + w * 128;               // writer row (lane 31)
    float* ringw1 = ringw0 + 8 * 128;
    const float* ringr0 = ring + (w - 1) * 128;   // reader row (lane 0, w>0)
    const float* ringr1 = ringr0 + 8 * 128;

    float lf0 = BIGF, lf1 = BIGF;                       // D[r+1][c] running
    float dg0 = (t == 0) ? 0.f : BIGF, dg1 = dg0;       // diag carry D[r][c]

    // initial window: columns [0,16) of this lane's rows (both batches)
#pragma unroll
    for (int q = 0; q < 4; q++) {
        asm volatile("cp.async.cg.shared.global [%0], [%1], 16;"
                     :: "r"(dws0 + 16 * q), "l"(gb0 + 4 * q));
        asm volatile("cp.async.cg.shared.global [%0], [%1], 16;"
                     :: "r"(dws1 + 16 * q), "l"(gb1 + 4 * q));
    }
    asm volatile("cp.async.commit_group;");

    for (int ph = 0; ph < NPH; ++ph) {
        const int t0 = 16 * ph - 48 * w;
        const int lc = t0 + 16;              // prefetch col base (for next phase)
        if (lc >= 0 && lc <= 240) {
            uint32_t d0 = dws0 + ((lc & 63) << 2);
            uint32_t d1 = dws1 + ((lc & 63) << 2);
            const float* g0 = gb0 + lc;
            const float* g1 = gb1 + lc;
#pragma unroll
            for (int q = 0; q < 4; q++) {
                asm volatile("cp.async.cg.shared.global [%0], [%1], 16;"
                             :: "r"(d0 + 16 * q), "l"(g0 + 4 * q));
                asm volatile("cp.async.cg.shared.global [%0], [%1], 16;"
                             :: "r"(d1 + 16 * q), "l"(g1 + 4 * q));
            }
        }
        asm volatile("cp.async.commit_group;");
        asm volatile("cp.async.wait_group 1;");
        __syncthreads();

        if (t0 < 0 || t0 > 286) continue;    // warp idle this phase (barrier done)

        // lane 0 boundary preload: up(c) for c in [t0, t0+15]
        float bnd0[16], bnd1[16];
        if (l == 0) {
            if (w == 0) {
#pragma unroll
                for (int q = 0; q < 16; q++) { bnd0[q] = BIGF; bnd1[q] = BIGF; }
            } else {
                const int base = t0 & 127;   // mult of 16, no wrap within 16
#pragma unroll
                for (int q = 0; q < 4; q++) {
                    float4 v0 = *(const float4*)(ringr0 + base + 4 * q);
                    float4 v1 = *(const float4*)(ringr1 + base + 4 * q);
                    bnd0[4 * q + 0] = v0.x; bnd0[4 * q + 1] = v0.y;
                    bnd0[4 * q + 2] = v0.z; bnd0[4 * q + 3] = v0.w;
                    bnd1[4 * q + 0] = v1.x; bnd1[4 * q + 1] = v1.y;
                    bnd1[4 * q + 2] = v1.z; bnd1[4 * q + 3] = v1.w;
                }
            }
        }

#pragma unroll
        for (int s = 0; s < 16; s++) {
            const int c = t0 + s - l;                  // dist col this lane
            const bool act = ((unsigned)c < 256u);
            float up0 = __shfl_up_sync(0xffffffffu, lf0, 1);
            float up1 = __shfl_up_sync(0xffffffffu, lf1, 1);
            if (l == 0) { up0 = bnd0[s]; up1 = bnd1[s]; }
            const float dq0 = dwr0[c & 63];
            const float dq1 = dwr1[c & 63];

            float a0 = fminf(up0, lf0), b0 = fmaxf(up0, lf0);
            float mn0 = fminf(a0, dg0);
            float mx0 = fmaxf(b0, dg0);
            float md0 = fmaxf(a0, fminf(b0, dg0));
            float a1 = fminf(up1, lf1), b1 = fmaxf(up1, lf1);
            float mn1 = fminf(a1, dg1);
            float mx1 = fmaxf(b1, dg1);
            float md1 = fmaxf(a1, fminf(b1, dg1));
            float s0 = 1.0f + __expf(mn0 - md0) + __expf(mn0 - mx0);
            float s1 = 1.0f + __expf(mn1 - md1) + __expf(mn1 - mx1);
            float nv0 = dq0 + mn0 - __logf(s0);
            float nv1 = dq1 + mn1 - __logf(s1);

            if (act) {
                if (l == 31) {
                    ringw0[c & 127] = nv0;
                    ringw1[c & 127] = nv1;
                    if (w == 7 && c == 255) {
                        g_partial[2 * bb] = nv0;
                        g_partial[2 * bb + 1] = nv1;
                    }
                }
                dg0 = up0; dg1 = up1;
                lf0 = nv0; lf1 = nv1;
            }
        }
    }
}

// ---------------------------------------------------------------------------
// Kernel 3: mean over batches -> scalar output.
// ---------------------------------------------------------------------------
__global__ __launch_bounds__(256) void reduce_kernel(float* __restrict__ out) {
    __shared__ float sb[256];
    int t = threadIdx.x;
    sb[t] = g_partial[t];
    __syncthreads();
    for (int s = 128; s > 0; s >>= 1) {
        if (t < s) sb[t] += sb[t + s];
        __syncthreads();
    }
    if (t == 0) out[0] = sb[0] * (1.0f / BATCH);
}

extern "C" void kernel_launch(void* const* d_in, const int* in_sizes, int n_in,
                              void* d_out, int out_size) {
    (void)in_sizes; (void)n_in; (void)out_size;
    const float* x = (const float*)d_in[0];
    const float* y = (const float*)d_in[1];
    float* out = (float*)d_out;

    cudaFuncSetAttribute(dtw_kernel, cudaFuncAttributeMaxDynamicSharedMemorySize,
                         SMEM_DP);

    dist_kernel<<<BATCH, 256>>>(x, y);
    dtw_kernel<<<BATCH / 2, 256, SMEM_DP>>>();
    reduce_kernel<<<1, 256>>>(out);
}